// round 1
// baseline (speedup 1.0000x reference)
#include <cuda_runtime.h>

#define H        128
#define TE       128      // edges per block
#define TEP      132      // smem pitch for [k][e] activation tiles (pad vs bank conflicts)
#define THREADS  256

// Aggregation scratch (allocation-free rule: __device__ globals)
__device__ float g_sum[65536];
__device__ float g_cnt[65536];

// ---------------------------------------------------------------------------
// Node kernel: velocity + zero aggregation scratch
// ---------------------------------------------------------------------------
__global__ void node_kernel(const float* __restrict__ theta,
                            const float* __restrict__ v0p,
                            float* __restrict__ out, int N) {
    int i = blockIdx.x * blockDim.x + threadIdx.x;
    if (i < N) {
        float s, c;
        sincosf(theta[i], &s, &c);
        float v0 = *v0p;
        out[2 * i + 0] = v0 * c;
        out[2 * i + 1] = v0 * s;
        g_sum[i] = 0.0f;
        g_cnt[i] = 0.0f;
    }
}

// ---------------------------------------------------------------------------
// Fused per-edge MLP. Activations live in SMEM transposed [k][e] (pitch TEP).
// Each thread owns an 8(edge) x 8(neuron) register tile; accumulators are
// packed pairs along the edge dim and driven with fma.rn.f32x2.
// ---------------------------------------------------------------------------
template<int K, bool RELU>
__device__ __forceinline__ void layer(const float* __restrict__ gW,
                                      const float* __restrict__ gB,
                                      const float* __restrict__ sIn,
                                      float* __restrict__ sOut,
                                      float* __restrict__ sW,
                                      float* __restrict__ sBias,
                                      int tid) {
    // Stage weights K*H (row-major [k][j]) into SMEM, coalesced float4
    constexpr int NV = K * H / 4;
    const float4* gW4 = (const float4*)gW;
    float4* sW4 = (float4*)sW;
    #pragma unroll 4
    for (int i = tid; i < NV; i += THREADS) sW4[i] = gW4[i];
    if (tid < H) sBias[tid] = gB[tid];
    __syncthreads();

    const int tx = tid & 15, ty = tid >> 4;
    const int e0 = tx * 8, j0 = ty * 8;

    unsigned long long acc[4][8];
    #pragma unroll
    for (int jj = 0; jj < 8; jj++) {
        float b = sBias[j0 + jj];
        unsigned long long bp;
        asm("mov.b64 %0,{%1,%1};" : "=l"(bp) : "f"(b));
        #pragma unroll
        for (int ee = 0; ee < 4; ee++) acc[ee][jj] = bp;
    }

    #pragma unroll 2
    for (int k = 0; k < K; k++) {
        const float* ar = sIn + k * TEP + e0;
        ulonglong2 a01 = *(const ulonglong2*)ar;        // edges e0..e0+3
        ulonglong2 a23 = *(const ulonglong2*)(ar + 4);  // edges e0+4..e0+7
        unsigned long long ap[4] = {a01.x, a01.y, a23.x, a23.y};

        const float4* wr = (const float4*)(sW + k * H + j0);
        float4 w0 = wr[0], w1 = wr[1];
        float wv[8] = {w0.x, w0.y, w0.z, w0.w, w1.x, w1.y, w1.z, w1.w};

        #pragma unroll
        for (int jj = 0; jj < 8; jj++) {
            unsigned long long wp;
            asm("mov.b64 %0,{%1,%1};" : "=l"(wp) : "f"(wv[jj]));
            #pragma unroll
            for (int ee = 0; ee < 4; ee++)
                asm("fma.rn.f32x2 %0,%1,%2,%0;"
                    : "+l"(acc[ee][jj]) : "l"(ap[ee]), "l"(wp));
        }
    }

    // Store transposed ([j][e]) with optional ReLU, float4 stores
    #pragma unroll
    for (int jj = 0; jj < 8; jj++) {
        float ov[8];
        #pragma unroll
        for (int ee = 0; ee < 4; ee++) {
            float lo, hi;
            asm("mov.b64 {%0,%1},%2;" : "=f"(lo), "=f"(hi) : "l"(acc[ee][jj]));
            if (RELU) { lo = fmaxf(lo, 0.0f); hi = fmaxf(hi, 0.0f); }
            ov[2 * ee + 0] = lo;
            ov[2 * ee + 1] = hi;
        }
        float* orow = sOut + (j0 + jj) * TEP + e0;
        *(float4*)(orow)     = make_float4(ov[0], ov[1], ov[2], ov[3]);
        *(float4*)(orow + 4) = make_float4(ov[4], ov[5], ov[6], ov[7]);
    }
    __syncthreads();
}

__global__ __launch_bounds__(THREADS, 1)
void edge_kernel(const float* __restrict__ x, const float* __restrict__ theta,
                 const float* __restrict__ W0, const float* __restrict__ b0,
                 const float* __restrict__ W1, const float* __restrict__ b1,
                 const float* __restrict__ W2, const float* __restrict__ b2,
                 const float* __restrict__ W3, const float* __restrict__ b3,
                 const int* __restrict__ src, const int* __restrict__ dst,
                 int E) {
    extern __shared__ float sm[];
    float* sA    = sm;               // [H][TEP]
    float* sB    = sA + H * TEP;     // [H][TEP]
    float* sW    = sB + H * TEP;     // [H][H] (current layer)
    float* sBias = sW + H * H;       // [H]
    float* sW3   = sBias + H;        // [H]

    const int tid  = threadIdx.x;
    const int base = blockIdx.x * TE;

    if (tid < H) sW3[tid] = W3[tid];

    // ---- per-edge feature construction into sA rows 0..3 ----
    if (tid < TE) {
        int e = base + tid;
        float dx = 0.f, dy = 0.f, c = 0.f, s = 0.f;
        if (e < E) {
            int is = src[e], id = dst[e];
            float xs = x[2 * is], ys = x[2 * is + 1];
            float xd = x[2 * id], yd = x[2 * id + 1];
            float ths = theta[is], thd = theta[id];
            float sn, cn; sincosf(thd - ths, &sn, &cn);
            float ss, cs; sincosf(ths, &ss, &cs);
            float drx = xd - xs, dry = yd - ys;
            dx =  drx * cs + dry * ss;
            dy = -drx * ss + dry * cs;
            c = cn; s = sn;
        }
        sA[0 * TEP + tid] = dx;
        sA[1 * TEP + tid] = dy;
        sA[2 * TEP + tid] = c;
        sA[3 * TEP + tid] = s;
    }
    __syncthreads();

    layer<4, true>(W0, b0, sA, sB, sW, sBias, tid);   // feat -> h0   (sB)
    layer<H, true>(W1, b1, sB, sA, sW, sBias, tid);   // h0   -> h1   (sA)
    layer<H, true>(W2, b2, sA, sB, sW, sBias, tid);   // h1   -> h2   (sB)

    // ---- final 128 -> 1 + scatter-add ----
    if (tid < TE) {
        int e = base + tid;
        if (e < E) {
            float sum = b3[0];
            #pragma unroll 8
            for (int k = 0; k < H; k++) sum += sB[k * TEP + tid] * sW3[k];
            int d = dst[e];
            atomicAdd(&g_sum[d], sum);
            atomicAdd(&g_cnt[d], 1.0f);
        }
    }
}

// ---------------------------------------------------------------------------
// Finalize: torque = sum / max(cnt, 1)
// ---------------------------------------------------------------------------
__global__ void torque_kernel(float* __restrict__ out, int N) {
    int i = blockIdx.x * blockDim.x + threadIdx.x;
    if (i < N) out[2 * N + i] = g_sum[i] / fmaxf(g_cnt[i], 1.0f);
}

// ---------------------------------------------------------------------------
extern "C" void kernel_launch(void* const* d_in, const int* in_sizes, int n_in,
                              void* d_out, int out_size) {
    const float* x     = (const float*)d_in[0];
    const float* theta = (const float*)d_in[1];
    const float* v0    = (const float*)d_in[2];
    const float* W0    = (const float*)d_in[3];
    const float* b0    = (const float*)d_in[4];
    const float* W1    = (const float*)d_in[5];
    const float* b1    = (const float*)d_in[6];
    const float* W2    = (const float*)d_in[7];
    const float* b2    = (const float*)d_in[8];
    const float* W3    = (const float*)d_in[9];
    const float* b3    = (const float*)d_in[10];
    const int*   src   = (const int*)d_in[11];
    const int*   dst   = (const int*)d_in[12];

    int N = in_sizes[1];   // theta has N elements
    int E = in_sizes[11];  // src has E elements
    float* out = (float*)d_out;

    size_t smem = (size_t)(2 * H * TEP + H * H + 2 * H) * sizeof(float);
    cudaFuncSetAttribute(edge_kernel,
                         cudaFuncAttributeMaxDynamicSharedMemorySize, (int)smem);

    node_kernel<<<(N + 255) / 256, 256>>>(theta, v0, out, N);
    edge_kernel<<<(E + TE - 1) / TE, THREADS, smem>>>(
        x, theta, W0, b0, W1, b1, W2, b2, W3, b3, src, dst, E);
    torque_kernel<<<(N + 255) / 256, 256>>>(out, N);
}

// round 3
// speedup vs baseline: 3.4679x; 3.4679x over previous
#include <cuda_runtime.h>
#include <cstdint>

#define H        128
#define TE       128
#define THREADS  256
#define PITCH    132
#define GRID_P   148

// Aggregation scratch (allocation-free rule: __device__ globals)
__device__ float g_sum[65536];
__device__ float g_cnt[65536];

// SMEM float offsets
#define OFF_ACT 0               // [128][PITCH]           16896 floats
#define OFF_WF0 16896           // frag-major W0 (KC=1)    1024 floats
#define OFF_WF1 17920           // frag-major W1 (KC=16)  16384 floats
#define OFF_WF2 34304           // frag-major W2 (KC=16)  16384 floats
#define OFF_B0  50688
#define OFF_B1  50816
#define OFF_B2  50944
#define OFF_W3  51072
#define OFF_B3  51200
#define SMEM_FLOATS 51204       // ~200 KB

__device__ __forceinline__ uint32_t tf32_bits(float x) {
    uint32_t u; asm("cvt.rna.tf32.f32 %0, %1;" : "=r"(u) : "f"(x)); return u;
}
__device__ __forceinline__ float tf32f(float x) {
    return __uint_as_float(tf32_bits(x));
}

__device__ __forceinline__ void mma8(float* d, const uint32_t* a,
                                     uint32_t b0, uint32_t b1) {
    asm volatile("mma.sync.aligned.m16n8k8.row.col.f32.tf32.tf32.f32 "
        "{%0,%1,%2,%3}, {%4,%5,%6,%7}, {%8,%9}, {%0,%1,%2,%3};"
        : "+f"(d[0]), "+f"(d[1]), "+f"(d[2]), "+f"(d[3])
        : "r"(a[0]), "r"(a[1]), "r"(a[2]), "r"(a[3]), "r"(b0), "r"(b1));
}

// Stage W[K][H] (row-major) into fragment-major layout:
// WF[((kc*8 + ncp)*32 + lane)*4 + r] where
//   r=0: b0 of even n-chunk, r=1: b1 even, r=2: b0 odd, r=3: b1 odd
//   b0 = W[kc*8 + lane%4][nc*8 + lane/4],  b1 = +4 in k
__device__ void stage_w(const float* __restrict__ W, int KC, int Kreal,
                        float* __restrict__ WF, int tid) {
    int total = KC * 1024;
    for (int idx = tid; idx < total; idx += THREADS) {
        int rr   = idx & 3;
        int lane = (idx >> 2) & 31;
        int ncp  = (idx >> 7) & 7;
        int kc   = idx >> 10;
        int k = kc * 8 + (lane & 3) + ((rr & 1) << 2);
        int n = (2 * ncp + (rr >> 1)) * 8 + (lane >> 2);
        float w = (k < Kreal) ? W[k * H + n] : 0.0f;
        WF[idx] = tf32f(w);
    }
}

// One MLP layer on the 128x128 ACT tile, in place.
// Warp tile: m0 (64 rows) x n0 (32 cols). acc = bias-free GEMM, epilogue adds
// bias + ReLU (+ tf32 round if feeding another mma layer).
template<int KC, bool TF32OUT>
__device__ __forceinline__ void layer_mma(float* __restrict__ sm, int wfOff,
                                          int biasOff, int m0, int n0, int lane) {
    float acc[4][4][4];
    #pragma unroll
    for (int mc = 0; mc < 4; mc++)
        #pragma unroll
        for (int nc = 0; nc < 4; nc++)
            #pragma unroll
            for (int i = 0; i < 4; i++) acc[mc][nc][i] = 0.0f;

    const int r = lane >> 2, c = lane & 3;
    const float* act = sm + OFF_ACT;
    const float4* wf = (const float4*)(sm + wfOff);

    #pragma unroll
    for (int kc = 0; kc < KC; kc++) {
        uint32_t a[4][4];
        #pragma unroll
        for (int mc = 0; mc < 4; mc++) {
            const float* p = act + (m0 + 16 * mc + r) * PITCH + kc * 8 + c;
            a[mc][0] = __float_as_uint(p[0]);
            a[mc][1] = __float_as_uint(p[8 * PITCH]);
            a[mc][2] = __float_as_uint(p[4]);
            a[mc][3] = __float_as_uint(p[8 * PITCH + 4]);
        }
        uint32_t b[8];
        #pragma unroll
        for (int l = 0; l < 2; l++) {
            float4 v = wf[(kc * 8 + (n0 >> 4) + l) * 32 + lane];
            b[l * 4 + 0] = __float_as_uint(v.x);
            b[l * 4 + 1] = __float_as_uint(v.y);
            b[l * 4 + 2] = __float_as_uint(v.z);
            b[l * 4 + 3] = __float_as_uint(v.w);
        }
        #pragma unroll
        for (int mc = 0; mc < 4; mc++)
            #pragma unroll
            for (int nc = 0; nc < 4; nc++) {
                int bi = (nc >> 1) * 4 + (nc & 1) * 2;
                mma8(acc[mc][nc], a[mc], b[bi], b[bi + 1]);
            }
    }

    __syncthreads();   // everyone done READING ACT before in-place overwrite

    const int q = lane & 3;
    const float* bias = sm + biasOff;
    #pragma unroll
    for (int mc = 0; mc < 4; mc++) {
        #pragma unroll
        for (int nc = 0; nc < 4; nc++) {
            int col = n0 + nc * 8 + 2 * q;
            float bb0 = bias[col], bb1 = bias[col + 1];
            float v0 = fmaxf(acc[mc][nc][0] + bb0, 0.0f);
            float v1 = fmaxf(acc[mc][nc][1] + bb1, 0.0f);
            float v2 = fmaxf(acc[mc][nc][2] + bb0, 0.0f);
            float v3 = fmaxf(acc[mc][nc][3] + bb1, 0.0f);
            if (TF32OUT) { v0 = tf32f(v0); v1 = tf32f(v1); v2 = tf32f(v2); v3 = tf32f(v3); }
            int row0 = m0 + 16 * mc + r;
            *(float2*)(sm + OFF_ACT + row0 * PITCH + col)       = make_float2(v0, v1);
            *(float2*)(sm + OFF_ACT + (row0 + 8) * PITCH + col) = make_float2(v2, v3);
        }
    }
    __syncthreads();   // writes visible
}

// ---------------------------------------------------------------------------
__global__ void node_kernel(const float* __restrict__ theta,
                            const float* __restrict__ v0p,
                            float* __restrict__ out, int N) {
    int i = blockIdx.x * blockDim.x + threadIdx.x;
    if (i < N) {
        float s, c;
        sincosf(theta[i], &s, &c);
        float v0 = *v0p;
        out[2 * i + 0] = v0 * c;
        out[2 * i + 1] = v0 * s;
        g_sum[i] = 0.0f;
        g_cnt[i] = 0.0f;
    }
}

// ---------------------------------------------------------------------------
__global__ __launch_bounds__(THREADS, 1)
void edge_kernel(const float* __restrict__ x, const float* __restrict__ theta,
                 const float* __restrict__ W0, const float* __restrict__ b0,
                 const float* __restrict__ W1, const float* __restrict__ b1,
                 const float* __restrict__ W2, const float* __restrict__ b2,
                 const float* __restrict__ W3, const float* __restrict__ b3,
                 const int* __restrict__ src, const int* __restrict__ dst,
                 int E, int nTiles) {
    extern __shared__ __align__(16) float sm[];
    const int tid  = threadIdx.x;
    const int wid  = tid >> 5;
    const int lane = tid & 31;

    // --- stage weights (once per CTA) ---
    stage_w(W0, 1, 4,   sm + OFF_WF0, tid);
    stage_w(W1, 16, 128, sm + OFF_WF1, tid);
    stage_w(W2, 16, 128, sm + OFF_WF2, tid);
    for (int i = tid; i < H; i += THREADS) {
        sm[OFF_B0 + i] = b0[i];
        sm[OFF_B1 + i] = b1[i];
        sm[OFF_B2 + i] = b2[i];
        sm[OFF_W3 + i] = W3[i];
    }
    if (tid == 0) sm[OFF_B3] = b3[0];
    __syncthreads();

    const int m0 = (wid & 1) * 64;
    const int n0 = (wid >> 1) * 32;

    for (int tile = blockIdx.x; tile < nTiles; tile += gridDim.x) {
        const int ebase = tile * TE;

        // ---- features -> ACT rows, cols 0..7 (4 real + 4 zero-pad) ----
        if (tid < TE) {
            int e = ebase + tid;
            float dx = 0.f, dy = 0.f, cc = 0.f, ss = 0.f;
            if (e < E) {
                int is = src[e], id = dst[e];
                float xs = x[2 * is], ys = x[2 * is + 1];
                float xd = x[2 * id], yd = x[2 * id + 1];
                float ths = theta[is], thd = theta[id];
                float sn, cn; sincosf(thd - ths, &sn, &cn);
                float s0, c0; sincosf(ths, &s0, &c0);
                float drx = xd - xs, dry = yd - ys;
                dx =  drx * c0 + dry * s0;
                dy = -drx * s0 + dry * c0;
                cc = cn; ss = sn;
            }
            float* rp = sm + OFF_ACT + tid * PITCH;
            rp[0] = tf32f(dx); rp[1] = tf32f(dy);
            rp[2] = tf32f(cc); rp[3] = tf32f(ss);
            rp[4] = 0.f; rp[5] = 0.f; rp[6] = 0.f; rp[7] = 0.f;
        }
        __syncthreads();

        layer_mma<1,  true >(sm, OFF_WF0, OFF_B0, m0, n0, lane);
        layer_mma<16, true >(sm, OFF_WF1, OFF_B1, m0, n0, lane);
        layer_mma<16, false>(sm, OFF_WF2, OFF_B2, m0, n0, lane);

        // ---- final 128 -> 1 dot + scatter-add (bank-rotated reads) ----
        if (tid < TE) {
            int e = ebase + tid;
            if (e < E) {
                const float* row = sm + OFF_ACT + tid * PITCH;
                float s = sm[OFF_B3];
                #pragma unroll
                for (int i = 0; i < 32; i++) {
                    int j = (((lane >> 3) + i) & 31) * 4;
                    float4 hv = *(const float4*)(row + j);
                    float4 wv = *(const float4*)(sm + OFF_W3 + j);
                    s += hv.x * wv.x + hv.y * wv.y + hv.z * wv.z + hv.w * wv.w;
                }
                int d = dst[e];
                atomicAdd(&g_sum[d], s);
                atomicAdd(&g_cnt[d], 1.0f);
            }
        }
        __syncthreads();   // dot reads done before next tile's feature writes
    }
}

// ---------------------------------------------------------------------------
__global__ void torque_kernel(float* __restrict__ out, int N) {
    int i = blockIdx.x * blockDim.x + threadIdx.x;
    if (i < N) out[2 * N + i] = g_sum[i] / fmaxf(g_cnt[i], 1.0f);
}

// ---------------------------------------------------------------------------
extern "C" void kernel_launch(void* const* d_in, const int* in_sizes, int n_in,
                              void* d_out, int out_size) {
    const float* x     = (const float*)d_in[0];
    const float* theta = (const float*)d_in[1];
    const float* v0    = (const float*)d_in[2];
    const float* W0    = (const float*)d_in[3];
    const float* b0    = (const float*)d_in[4];
    const float* W1    = (const float*)d_in[5];
    const float* b1    = (const float*)d_in[6];
    const float* W2    = (const float*)d_in[7];
    const float* b2    = (const float*)d_in[8];
    const float* W3    = (const float*)d_in[9];
    const float* b3    = (const float*)d_in[10];
    const int*   src   = (const int*)d_in[11];
    const int*   dst   = (const int*)d_in[12];

    int N = in_sizes[1];
    int E = in_sizes[11];
    int nTiles = (E + TE - 1) / TE;
    float* out = (float*)d_out;

    size_t smem = (size_t)SMEM_FLOATS * sizeof(float);
    cudaFuncSetAttribute(edge_kernel,
                         cudaFuncAttributeMaxDynamicSharedMemorySize, (int)smem);

    int grid = GRID_P;
    if (nTiles < grid) grid = nTiles;

    node_kernel<<<(N + 255) / 256, 256>>>(theta, v0, out, N);
    edge_kernel<<<grid, THREADS, smem>>>(
        x, theta, W0, b0, W1, b1, W2, b2, W3, b3, src, dst, E, nTiles);
    torque_kernel<<<(N + 255) / 256, 256>>>(out, N);
}

// round 4
// speedup vs baseline: 3.5553x; 1.0252x over previous
#include <cuda_runtime.h>
#include <cstdint>

#define H        128
#define TE       128
#define THREADS  256
#define GRID_P   148

// Aggregation scratch (allocation-free rule: __device__ globals)
__device__ float g_sum[65536];
__device__ float g_cnt[65536];

// SMEM float offsets
#define OFF_FACT 0          // fragment-major ACT: 16384 floats (64KB)
#define OFF_WF0  16384      // frag-major W0 (KC=1)  1024 floats
#define OFF_WF1  17408      // frag-major W1 (KC=16) 16384 floats
#define OFF_WF2  33792      // frag-major W2 (KC=16) 16384 floats
#define OFF_B0   50176
#define OFF_B1   50304
#define OFF_B2   50432
#define OFF_W3   50560
#define OFF_RED  50688      // 512 floats: 4 n-groups x 128 rows
#define OFF_B3   51200
#define SMEM_FLOATS 51204   // ~200KB

__device__ __forceinline__ uint32_t tf32_bits(float x) {
    uint32_t u; asm("cvt.rna.tf32.f32 %0, %1;" : "=r"(u) : "f"(x)); return u;
}
__device__ __forceinline__ float tf32f(float x) {
    return __uint_as_float(tf32_bits(x));
}

__device__ __forceinline__ void mma8(float* d, const uint32_t* a,
                                     uint32_t b0, uint32_t b1) {
    asm volatile("mma.sync.aligned.m16n8k8.row.col.f32.tf32.tf32.f32 "
        "{%0,%1,%2,%3}, {%4,%5,%6,%7}, {%8,%9}, {%0,%1,%2,%3};"
        : "+f"(d[0]), "+f"(d[1]), "+f"(d[2]), "+f"(d[3])
        : "r"(a[0]), "r"(a[1]), "r"(a[2]), "r"(a[3]), "r"(b0), "r"(b1));
}

// Stage W[K][H] (row-major) into B-fragment-major layout (same as R3):
// WF[((kc*8 + ncp)*32 + lane)*4 + r],
//   r=0: b0 even n-chunk, r=1: b1 even, r=2: b0 odd, r=3: b1 odd
//   b0 = W[kc*8 + lane%4][nc*8 + lane/4], b1 = +4 in k
__device__ void stage_w(const float* __restrict__ W, int KC, int Kreal,
                        float* __restrict__ WF, int tid) {
    int total = KC * 1024;
    for (int idx = tid; idx < total; idx += THREADS) {
        int rr   = idx & 3;
        int lane = (idx >> 2) & 31;
        int ncp  = (idx >> 7) & 7;
        int kc   = idx >> 10;
        int k = kc * 8 + (lane & 3) + ((rr & 1) << 2);
        int n = (2 * ncp + (rr >> 1)) * 8 + (lane >> 2);
        float w = (k < Kreal) ? W[k * H + n] : 0.0f;
        WF[idx] = tf32f(w);
    }
}

// Mainloop: accumulate GEMM over KC k-chunks into acc[4][4][4].
// A read as float4 fragments from FACT (conflict-free LDS.128).
template<int KC>
__device__ __forceinline__ void layer_main(const float* __restrict__ sm,
                                           int wfOff, int m0, int n0, int lane,
                                           float acc[4][4][4]) {
    #pragma unroll
    for (int mc = 0; mc < 4; mc++)
        #pragma unroll
        for (int nc = 0; nc < 4; nc++)
            #pragma unroll
            for (int i = 0; i < 4; i++) acc[mc][nc][i] = 0.0f;

    const float4* fact4 = (const float4*)(sm + OFF_FACT);
    const float4* wf    = (const float4*)(sm + wfOff);
    const int mbb = m0 >> 4;

    #pragma unroll
    for (int kc = 0; kc < KC; kc++) {
        uint32_t a[4][4];
        #pragma unroll
        for (int mc = 0; mc < 4; mc++) {
            float4 v = fact4[((mbb + mc) * 16 + kc) * 32 + lane];
            a[mc][0] = __float_as_uint(v.x);
            a[mc][1] = __float_as_uint(v.y);
            a[mc][2] = __float_as_uint(v.z);
            a[mc][3] = __float_as_uint(v.w);
        }
        uint32_t b[8];
        #pragma unroll
        for (int l = 0; l < 2; l++) {
            float4 v = wf[(kc * 8 + (n0 >> 4) + l) * 32 + lane];
            b[l * 4 + 0] = __float_as_uint(v.x);
            b[l * 4 + 1] = __float_as_uint(v.y);
            b[l * 4 + 2] = __float_as_uint(v.z);
            b[l * 4 + 3] = __float_as_uint(v.w);
        }
        #pragma unroll
        for (int mc = 0; mc < 4; mc++)
            #pragma unroll
            for (int nc = 0; nc < 4; nc++) {
                int bi = (nc >> 1) * 4 + (nc & 1) * 2;
                mma8(acc[mc][nc], a[mc], b[bi], b[bi + 1]);
            }
    }
}

// Epilogue: relu(acc + bias), tf32-round, write fragment-major into FACT.
// Value (row,col): mb=row>>4, rr=row&7, i=((row>>3)&1)+2*((col>>2)&1),
// lane=rr*4+(col&3); addr=((mb*16+(col>>3))*32+lane)*4+i.
__device__ __forceinline__ void epi_write(float* __restrict__ sm, int biasOff,
                                          int m0, int n0, int lane,
                                          const float acc[4][4][4]) {
    const int r = lane >> 2, q = lane & 3;
    const float* bias = sm + biasOff;
    #pragma unroll
    for (int mc = 0; mc < 4; mc++) {
        int mb = (m0 >> 4) + mc;
        #pragma unroll
        for (int nc = 0; nc < 4; nc++) {
            int col = n0 + 8 * nc + 2 * q;
            float bb0 = bias[col], bb1 = bias[col + 1];
            float v0 = tf32f(fmaxf(acc[mc][nc][0] + bb0, 0.0f));  // (r,   col)
            float v1 = tf32f(fmaxf(acc[mc][nc][1] + bb1, 0.0f));  // (r,   col+1)
            float v2 = tf32f(fmaxf(acc[mc][nc][2] + bb0, 0.0f));  // (r+8, col)
            float v3 = tf32f(fmaxf(acc[mc][nc][3] + bb1, 0.0f));  // (r+8, col+1)
            int kc = col >> 3;
            int base = ((mb * 16 + kc) * 32 + r * 4 + (col & 3)) * 4 + 2 * (q >> 1);
            *(float2*)(sm + OFF_FACT + base)     = make_float2(v0, v2); // i, i+1
            *(float2*)(sm + OFF_FACT + base + 4) = make_float2(v1, v3); // col+1
        }
    }
}

// ---------------------------------------------------------------------------
__global__ void node_kernel(const float* __restrict__ theta,
                            const float* __restrict__ v0p,
                            float* __restrict__ out, int N) {
    int i = blockIdx.x * blockDim.x + threadIdx.x;
    if (i < N) {
        float s, c;
        sincosf(theta[i], &s, &c);
        float v0 = *v0p;
        out[2 * i + 0] = v0 * c;
        out[2 * i + 1] = v0 * s;
        g_sum[i] = 0.0f;
        g_cnt[i] = 0.0f;
    }
}

// ---------------------------------------------------------------------------
__global__ __launch_bounds__(THREADS, 1)
void edge_kernel(const float* __restrict__ x, const float* __restrict__ theta,
                 const float* __restrict__ W0, const float* __restrict__ b0,
                 const float* __restrict__ W1, const float* __restrict__ b1,
                 const float* __restrict__ W2, const float* __restrict__ b2,
                 const float* __restrict__ W3, const float* __restrict__ b3,
                 const int* __restrict__ src, const int* __restrict__ dst,
                 int E, int nTiles) {
    extern __shared__ __align__(16) float sm[];
    const int tid  = threadIdx.x;
    const int wid  = tid >> 5;
    const int lane = tid & 31;

    // --- stage weights once per CTA ---
    stage_w(W0, 1,  4,   sm + OFF_WF0, tid);
    stage_w(W1, 16, 128, sm + OFF_WF1, tid);
    stage_w(W2, 16, 128, sm + OFF_WF2, tid);
    for (int i = tid; i < H; i += THREADS) {
        sm[OFF_B0 + i] = b0[i];
        sm[OFF_B1 + i] = b1[i];
        sm[OFF_B2 + i] = b2[i];
        sm[OFF_W3 + i] = W3[i];
    }
    if (tid == 0) sm[OFF_B3] = b3[0];
    __syncthreads();

    const int m0 = (wid & 1) * 64;
    const int n0 = (wid >> 1) * 32;
    const int ng = wid >> 1;           // n-group 0..3
    float acc[4][4][4];

    for (int tile = blockIdx.x; tile < nTiles; tile += gridDim.x) {
        const int ebase = tile * TE;

        // ---- features -> FACT kc=0 block (fragment layout), cols 0..7 ----
        if (tid < TE) {
            int e = ebase + tid;
            float v[8] = {0.f, 0.f, 0.f, 0.f, 0.f, 0.f, 0.f, 0.f};
            if (e < E) {
                int is = src[e], id = dst[e];
                float xs = x[2 * is], ys = x[2 * is + 1];
                float xd = x[2 * id], yd = x[2 * id + 1];
                float ths = theta[is], thd = theta[id];
                float sn, cn; sincosf(thd - ths, &sn, &cn);
                float s0, c0; sincosf(ths, &s0, &c0);
                float drx = xd - xs, dry = yd - ys;
                v[0] = tf32f( drx * c0 + dry * s0);
                v[1] = tf32f(-drx * s0 + dry * c0);
                v[2] = tf32f(cn);
                v[3] = tf32f(sn);
            }
            int mb = tid >> 4, rr = tid & 7, hi = (tid >> 3) & 1;
            #pragma unroll
            for (int col = 0; col < 8; col++) {
                int i = hi + 2 * (col >> 2);
                sm[OFF_FACT + ((mb * 16) * 32 + rr * 4 + (col & 3)) * 4 + i] = v[col];
            }
        }
        __syncthreads();

        // ---- layer 0 (K=8 incl pad) ----
        layer_main<1>(sm, OFF_WF0, m0, n0, lane, acc);
        __syncthreads();                       // all reads of kc0 done
        epi_write(sm, OFF_B0, m0, n0, lane, acc);
        __syncthreads();

        // ---- layer 1 ----
        layer_main<16>(sm, OFF_WF1, m0, n0, lane, acc);
        __syncthreads();                       // reads done before overwrite
        epi_write(sm, OFF_B1, m0, n0, lane, acc);
        __syncthreads();

        // ---- layer 2 + fused final dot (no smem writeback of h2) ----
        layer_main<16>(sm, OFF_WF2, m0, n0, lane, acc);
        {
            const int r = lane >> 2, q = lane & 3;
            #pragma unroll
            for (int mc = 0; mc < 4; mc++) {
                float pa = 0.f, pb = 0.f;
                #pragma unroll
                for (int nc = 0; nc < 4; nc++) {
                    int col = n0 + 8 * nc + 2 * q;
                    float bb0 = sm[OFF_B2 + col], bb1 = sm[OFF_B2 + col + 1];
                    float w3a = sm[OFF_W3 + col], w3b = sm[OFF_W3 + col + 1];
                    pa += fmaxf(acc[mc][nc][0] + bb0, 0.f) * w3a;
                    pa += fmaxf(acc[mc][nc][1] + bb1, 0.f) * w3b;
                    pb += fmaxf(acc[mc][nc][2] + bb0, 0.f) * w3a;
                    pb += fmaxf(acc[mc][nc][3] + bb1, 0.f) * w3b;
                }
                pa += __shfl_xor_sync(0xffffffffu, pa, 1);
                pa += __shfl_xor_sync(0xffffffffu, pa, 2);
                pb += __shfl_xor_sync(0xffffffffu, pb, 1);
                pb += __shfl_xor_sync(0xffffffffu, pb, 2);
                if (q == 0) {
                    int row = m0 + 16 * mc + r;
                    sm[OFF_RED + ng * 128 + row]     = pa;
                    sm[OFF_RED + ng * 128 + row + 8] = pb;
                }
            }
        }
        __syncthreads();

        // ---- combine n-group partials + scatter-add ----
        if (tid < TE) {
            int e = ebase + tid;
            if (e < E) {
                float msg = sm[OFF_RED + tid] + sm[OFF_RED + 128 + tid]
                          + sm[OFF_RED + 256 + tid] + sm[OFF_RED + 384 + tid]
                          + sm[OFF_B3];
                int d = dst[e];
                atomicAdd(&g_sum[d], msg);
                atomicAdd(&g_cnt[d], 1.0f);
            }
        }
        // next tile's feature write is ordered by the sync at loop top
        __syncthreads();
    }
}

// ---------------------------------------------------------------------------
__global__ void torque_kernel(float* __restrict__ out, int N) {
    int i = blockIdx.x * blockDim.x + threadIdx.x;
    if (i < N) out[2 * N + i] = g_sum[i] / fmaxf(g_cnt[i], 1.0f);
}

// ---------------------------------------------------------------------------
extern "C" void kernel_launch(void* const* d_in, const int* in_sizes, int n_in,
                              void* d_out, int out_size) {
    const float* x     = (const float*)d_in[0];
    const float* theta = (const float*)d_in[1];
    const float* v0    = (const float*)d_in[2];
    const float* W0    = (const float*)d_in[3];
    const float* b0    = (const float*)d_in[4];
    const float* W1    = (const float*)d_in[5];
    const float* b1    = (const float*)d_in[6];
    const float* W2    = (const float*)d_in[7];
    const float* b2    = (const float*)d_in[8];
    const float* W3    = (const float*)d_in[9];
    const float* b3    = (const float*)d_in[10];
    const int*   src   = (const int*)d_in[11];
    const int*   dst   = (const int*)d_in[12];

    int N = in_sizes[1];
    int E = in_sizes[11];
    int nTiles = (E + TE - 1) / TE;
    float* out = (float*)d_out;

    size_t smem = (size_t)SMEM_FLOATS * sizeof(float);
    cudaFuncSetAttribute(edge_kernel,
                         cudaFuncAttributeMaxDynamicSharedMemorySize, (int)smem);

    int grid = GRID_P;
    if (nTiles < grid) grid = nTiles;

    node_kernel<<<(N + 255) / 256, 256>>>(theta, v0, out, N);
    edge_kernel<<<grid, THREADS, smem>>>(
        x, theta, W0, b0, W1, b1, W2, b2, W3, b3, src, dst, E, nTiles);
    torque_kernel<<<(N + 255) / 256, 256>>>(out, N);
}

// round 6
// speedup vs baseline: 7.4320x; 2.0904x over previous
#include <cuda_runtime.h>
#include <cstdint>

#define H        128
#define TE       128
#define THREADS  256
#define GRID_P   296          // 2 CTAs per SM

// Aggregation scratch (allocation-free rule: __device__ globals)
__device__ float g_sum[65536];
__device__ float g_cnt[65536];

// SMEM word (u32/float) offsets
#define OFF_FACT 0            // fp16 frag-major ACT: 8 mb x 8 kc x 32 x 4 = 8192
#define OFF_WF0  8192         // fp16 frag-major W0 (1 kc)  : 1024
#define OFF_WF1  9216         // fp16 frag-major W1 (8 kc)  : 8192
#define OFF_WF2  17408        // fp16 frag-major W2 (8 kc)  : 8192
#define OFF_B0   25600
#define OFF_B1   25728
#define OFF_B2   25856
#define OFF_W3   25984
#define OFF_RED  26112        // 512 floats: 4 n-groups x 128 rows
#define OFF_B3   26624
#define SMEM_WORDS 26628      // ~104 KB -> 2 CTAs/SM

__device__ __forceinline__ uint32_t pk16(float lo, float hi) {
    uint32_t u;
    asm("cvt.rn.f16x2.f32 %0, %1, %2;" : "=r"(u) : "f"(hi), "f"(lo));
    return u;
}

__device__ __forceinline__ void mma16(float* d, const uint32_t* a,
                                      uint32_t b0, uint32_t b1) {
    asm volatile("mma.sync.aligned.m16n8k16.row.col.f32.f16.f16.f32 "
        "{%0,%1,%2,%3}, {%4,%5,%6,%7}, {%8,%9}, {%0,%1,%2,%3};"
        : "+f"(d[0]), "+f"(d[1]), "+f"(d[2]), "+f"(d[3])
        : "r"(a[0]), "r"(a[1]), "r"(a[2]), "r"(a[3]), "r"(b0), "r"(b1));
}

// Stage W[K][H] (row-major, fp32) into fp16 B-fragment-major:
// WFu[((kc*8 + ncp)*32 + lane)*4 + r]
//   c=lane&3, g=lane>>2; n=(2*ncp + (r>>1))*8 + g
//   kbase = kc*16 + 2*c + (r&1)*8; word = pack(W[kbase][n], W[kbase+1][n])
__device__ void stage_w(const float* __restrict__ W, int KC16, int Kreal,
                        uint32_t* __restrict__ WF, int tid) {
    int total = KC16 * 1024;
    for (int idx = tid; idx < total; idx += THREADS) {
        int r    = idx & 3;
        int lane = (idx >> 2) & 31;
        int ncp  = (idx >> 7) & 7;
        int kc   = idx >> 10;
        int c = lane & 3, g = lane >> 2;
        int n = (2 * ncp + (r >> 1)) * 8 + g;
        int kb = kc * 16 + 2 * c + ((r & 1) << 3);
        float lo = (kb     < Kreal) ? W[kb * H + n]       : 0.0f;
        float hi = (kb + 1 < Kreal) ? W[(kb + 1) * H + n] : 0.0f;
        WF[idx] = pk16(lo, hi);
    }
}

// Mainloop: acc += ACT * W over KC16 chunks of k=16.
template<int KC16>
__device__ __forceinline__ void layer_main(const uint32_t* __restrict__ smu,
                                           int wfOff, int m0, int n0, int lane,
                                           float acc[4][4][4]) {
    #pragma unroll
    for (int mc = 0; mc < 4; mc++)
        #pragma unroll
        for (int nc = 0; nc < 4; nc++)
            #pragma unroll
            for (int i = 0; i < 4; i++) acc[mc][nc][i] = 0.0f;

    const uint4* fact4 = (const uint4*)(smu + OFF_FACT);
    const uint4* wf    = (const uint4*)(smu + wfOff);
    const int mbb = m0 >> 4;

    #pragma unroll
    for (int kc = 0; kc < KC16; kc++) {
        uint32_t a[4][4];
        #pragma unroll
        for (int mc = 0; mc < 4; mc++) {
            uint4 v = fact4[((mbb + mc) * 8 + kc) * 32 + lane];
            a[mc][0] = v.x; a[mc][1] = v.y; a[mc][2] = v.z; a[mc][3] = v.w;
        }
        uint32_t b[8];
        #pragma unroll
        for (int l = 0; l < 2; l++) {
            uint4 v = wf[(kc * 8 + (n0 >> 4) + l) * 32 + lane];
            b[l * 4 + 0] = v.x; b[l * 4 + 1] = v.y;
            b[l * 4 + 2] = v.z; b[l * 4 + 3] = v.w;
        }
        #pragma unroll
        for (int mc = 0; mc < 4; mc++)
            #pragma unroll
            for (int nc = 0; nc < 4; nc++) {
                int bi = (nc >> 1) * 4 + (nc & 1) * 2;
                mma16(acc[mc][nc], a[mc], b[bi], b[bi + 1]);
            }
    }
}

// Epilogue: relu(acc+bias) -> fp16 pack -> A-fragment slots (lane-local!).
// Thread's acc (r,col),(r,col+1),(r+8,col),(r+8,col+1), col=n0+8nc+2q maps to
// lane'=lane, kc=col>>4, reg i = (row>>3) + 2*(nc&1) -> one uint4 per (mc, nc-pair).
__device__ __forceinline__ void epi_write(uint32_t* __restrict__ smu,
                                          const float* __restrict__ bias,
                                          int m0, int n0, int lane,
                                          const float acc[4][4][4]) {
    const int q = lane & 3;
    uint4* fact4 = (uint4*)(smu + OFF_FACT);
    #pragma unroll
    for (int mc = 0; mc < 4; mc++) {
        int mb = (m0 >> 4) + mc;
        #pragma unroll
        for (int p = 0; p < 2; p++) {              // nc pair (2p, 2p+1)
            uint32_t w[4];
            #pragma unroll
            for (int h = 0; h < 2; h++) {          // nc = 2p+h
                int nc = 2 * p + h;
                int col = n0 + 8 * nc + 2 * q;
                float bb0 = bias[col], bb1 = bias[col + 1];
                w[2 * h + 0] = pk16(fmaxf(acc[mc][nc][0] + bb0, 0.0f),
                                    fmaxf(acc[mc][nc][1] + bb1, 0.0f));
                w[2 * h + 1] = pk16(fmaxf(acc[mc][nc][2] + bb0, 0.0f),
                                    fmaxf(acc[mc][nc][3] + bb1, 0.0f));
            }
            int kc = (n0 >> 4) + p;
            fact4[(mb * 8 + kc) * 32 + lane] = make_uint4(w[0], w[1], w[2], w[3]);
        }
    }
}

// ---------------------------------------------------------------------------
__global__ void node_kernel(const float* __restrict__ theta,
                            const float* __restrict__ v0p,
                            float* __restrict__ out, int N) {
    int i = blockIdx.x * blockDim.x + threadIdx.x;
    if (i < N) {
        float s, c;
        sincosf(theta[i], &s, &c);
        float v0 = *v0p;
        out[2 * i + 0] = v0 * c;
        out[2 * i + 1] = v0 * s;
        g_sum[i] = 0.0f;
        g_cnt[i] = 0.0f;
    }
}

// ---------------------------------------------------------------------------
__global__ __launch_bounds__(THREADS, 2)
void edge_kernel(const float* __restrict__ x, const float* __restrict__ theta,
                 const float* __restrict__ W0, const float* __restrict__ b0,
                 const float* __restrict__ W1, const float* __restrict__ b1,
                 const float* __restrict__ W2, const float* __restrict__ b2,
                 const float* __restrict__ W3, const float* __restrict__ b3,
                 const int* __restrict__ src, const int* __restrict__ dst,
                 int E, int nTiles) {
    extern __shared__ __align__(16) uint32_t smu[];
    float* smf = (float*)smu;
    const int tid  = threadIdx.x;
    const int wid  = tid >> 5;
    const int lane = tid & 31;

    // --- stage weights (fp16) + biases (fp32) once per CTA ---
    stage_w(W0, 1, 4,   smu + OFF_WF0, tid);
    stage_w(W1, 8, 128, smu + OFF_WF1, tid);
    stage_w(W2, 8, 128, smu + OFF_WF2, tid);
    for (int i = tid; i < H; i += THREADS) {
        smf[OFF_B0 + i] = b0[i];
        smf[OFF_B1 + i] = b1[i];
        smf[OFF_B2 + i] = b2[i];
        smf[OFF_W3 + i] = W3[i];
    }
    if (tid == 0) smf[OFF_B3] = b3[0];
    __syncthreads();

    const int m0 = (wid & 1) * 64;
    const int n0 = (wid >> 1) * 32;
    const int ng = wid >> 1;
    float acc[4][4][4];

    for (int tile = blockIdx.x; tile < nTiles; tile += gridDim.x) {
        const int ebase = tile * TE;

        // ---- features -> FACT kc=0 (fragment layout), k=0..3 real, 4..15 pad ----
        if (tid < TE) {
            int e = ebase + tid;
            float v0f = 0.f, v1f = 0.f, v2f = 0.f, v3f = 0.f;
            if (e < E) {
                int is = src[e], id = dst[e];
                float xs = x[2 * is], ys = x[2 * is + 1];
                float xd = x[2 * id], yd = x[2 * id + 1];
                float ths = theta[is], thd = theta[id];
                float sn, cn; sincosf(thd - ths, &sn, &cn);
                float s0, c0; sincosf(ths, &s0, &c0);
                float drx = xd - xs, dry = yd - ys;
                v0f =  drx * c0 + dry * s0;
                v1f = -drx * s0 + dry * c0;
                v2f = cn; v3f = sn;
            }
            int mb = tid >> 4, row16 = tid & 15, r = row16 & 7, hi = row16 >> 3;
            uint32_t base = ((mb * 8) * 32 + r * 4) * 4;
            #pragma unroll
            for (int c = 0; c < 4; c++) {
                uint32_t w = (c == 0) ? pk16(v0f, v1f)
                           : (c == 1) ? pk16(v2f, v3f) : 0u;
                smu[OFF_FACT + base + c * 4 + hi]     = w;   // k<8
                smu[OFF_FACT + base + c * 4 + 2 + hi] = 0u;  // k>=8
            }
        }
        __syncthreads();

        // ---- layer 0 ----
        layer_main<1>(smu, OFF_WF0, m0, n0, lane, acc);
        __syncthreads();
        epi_write(smu, smf + OFF_B0, m0, n0, lane, acc);
        __syncthreads();

        // ---- layer 1 ----
        layer_main<8>(smu, OFF_WF1, m0, n0, lane, acc);
        __syncthreads();
        epi_write(smu, smf + OFF_B1, m0, n0, lane, acc);
        __syncthreads();

        // ---- layer 2 + fused final dot ----
        layer_main<8>(smu, OFF_WF2, m0, n0, lane, acc);
        {
            const int r = lane >> 2, q = lane & 3;
            #pragma unroll
            for (int mc = 0; mc < 4; mc++) {
                float pa = 0.f, pb = 0.f;
                #pragma unroll
                for (int nc = 0; nc < 4; nc++) {
                    int col = n0 + 8 * nc + 2 * q;
                    float bb0 = smf[OFF_B2 + col], bb1 = smf[OFF_B2 + col + 1];
                    float w3a = smf[OFF_W3 + col], w3b = smf[OFF_W3 + col + 1];
                    pa += fmaxf(acc[mc][nc][0] + bb0, 0.f) * w3a;
                    pa += fmaxf(acc[mc][nc][1] + bb1, 0.f) * w3b;
                    pb += fmaxf(acc[mc][nc][2] + bb0, 0.f) * w3a;
                    pb += fmaxf(acc[mc][nc][3] + bb1, 0.f) * w3b;
                }
                pa += __shfl_xor_sync(0xffffffffu, pa, 1);
                pa += __shfl_xor_sync(0xffffffffu, pa, 2);
                pb += __shfl_xor_sync(0xffffffffu, pb, 1);
                pb += __shfl_xor_sync(0xffffffffu, pb, 2);
                if (q == 0) {
                    int row = m0 + 16 * mc + r;
                    smf[OFF_RED + ng * 128 + row]     = pa;
                    smf[OFF_RED + ng * 128 + row + 8] = pb;
                }
            }
        }
        __syncthreads();

        // ---- combine partials + scatter-add ----
        if (tid < TE) {
            int e = ebase + tid;
            if (e < E) {
                float msg = smf[OFF_RED + tid] + smf[OFF_RED + 128 + tid]
                          + smf[OFF_RED + 256 + tid] + smf[OFF_RED + 384 + tid]
                          + smf[OFF_B3];
                int d = dst[e];
                atomicAdd(&g_sum[d], msg);
                atomicAdd(&g_cnt[d], 1.0f);
            }
        }
        __syncthreads();
    }
}

// ---------------------------------------------------------------------------
__global__ void torque_kernel(float* __restrict__ out, int N) {
    int i = blockIdx.x * blockDim.x + threadIdx.x;
    if (i < N) out[2 * N + i] = g_sum[i] / fmaxf(g_cnt[i], 1.0f);
}

// ---------------------------------------------------------------------------
extern "C" void kernel_launch(void* const* d_in, const int* in_sizes, int n_in,
                              void* d_out, int out_size) {
    const float* x     = (const float*)d_in[0];
    const float* theta = (const float*)d_in[1];
    const float* v0    = (const float*)d_in[2];
    const float* W0    = (const float*)d_in[3];
    const float* b0    = (const float*)d_in[4];
    const float* W1    = (const float*)d_in[5];
    const float* b1    = (const float*)d_in[6];
    const float* W2    = (const float*)d_in[7];
    const float* b2    = (const float*)d_in[8];
    const float* W3    = (const float*)d_in[9];
    const float* b3    = (const float*)d_in[10];
    const int*   src   = (const int*)d_in[11];
    const int*   dst   = (const int*)d_in[12];

    int N = in_sizes[1];
    int E = in_sizes[11];
    int nTiles = (E + TE - 1) / TE;
    float* out = (float*)d_out;

    size_t smem = (size_t)SMEM_WORDS * sizeof(uint32_t);
    cudaFuncSetAttribute(edge_kernel,
                         cudaFuncAttributeMaxDynamicSharedMemorySize, (int)smem);

    int grid = GRID_P;
    if (nTiles < grid) grid = nTiles;

    node_kernel<<<(N + 255) / 256, 256>>>(theta, v0, out, N);
    edge_kernel<<<grid, THREADS, smem>>>(
        x, theta, W0, b0, W1, b1, W2, b2, W3, b3, src, dst, E, nTiles);
    torque_kernel<<<(N + 255) / 256, 256>>>(out, N);
}